// round 16
// baseline (speedup 1.0000x reference)
#include <cuda_runtime.h>
#include <cuda_bf16.h>
#include <cstdint>
#include <cstddef>

#define SS 2048
#define DD 64
#define HH 16

// per-(bh,row, kt*2+warp_n) partial sums of exp: 32*2048*32 floats = 8MB
__device__ float g_rowpart[(size_t)32 * 2048 * 32];

static __device__ __forceinline__ uint32_t smem_u32(const void* p) {
    uint32_t a;
    asm("{ .reg .u64 t; cvta.to.shared.u64 t, %1; cvt.u32.u64 %0, t; }" : "=r"(a) : "l"(p));
    return a;
}

#define LDSM4(r0, r1, r2, r3, a) \
    asm volatile("ldmatrix.sync.aligned.m8n8.x4.shared.b16 {%0,%1,%2,%3}, [%4];" \
        : "=r"(r0), "=r"(r1), "=r"(r2), "=r"(r3) : "r"(a))

#define MMA16816(c, a, b) \
    asm volatile("mma.sync.aligned.m16n8k16.row.col.f32.bf16.bf16.f32 " \
        "{%0,%1,%2,%3}, {%4,%5,%6,%7}, {%8,%9}, {%0,%1,%2,%3};" \
        : "+f"((c)[0]), "+f"((c)[1]), "+f"((c)[2]), "+f"((c)[3]) \
        : "r"((a)[0]), "r"((a)[1]), "r"((a)[2]), "r"((a)[3]), "r"((b)[0]), "r"((b)[1]))

static __device__ __forceinline__ float2 ffma2(float2 a, float2 b, float2 c) {
    unsigned long long ua = *reinterpret_cast<unsigned long long*>(&a);
    unsigned long long ub = *reinterpret_cast<unsigned long long*>(&b);
    unsigned long long uc = *reinterpret_cast<unsigned long long*>(&c);
    unsigned long long ud;
    asm("fma.rn.f32x2 %0, %1, %2, %3;" : "=l"(ud) : "l"(ua), "l"(ub), "l"(uc));
    return *reinterpret_cast<float2*>(&ud);
}

// T5 bidirectional bucket, NUM_BUCKETS=32, MAX_DISTANCE=128 (exact int thresholds)
static __device__ __forceinline__ int rp_bucket(int rel) {
    int n = -rel;
    int ret = (n < 0) ? 16 : 0;
    n = abs(n);
    if (n < 8) return ret + n;
    return ret + 8 + (n >= 12) + (n >= 16) + (n >= 23) + (n >= 32)
                   + (n >= 46) + (n >= 64) + (n >= 91);
}

// split 8 f32 -> 8 bf16 hi + 8 bf16 lo
static __device__ __forceinline__ void split8(
    const float4 f0, const float4 f1, uint4* hi, uint4* lo)
{
    __nv_bfloat162 h0 = __float22bfloat162_rn(make_float2(f0.x, f0.y));
    __nv_bfloat162 h1 = __float22bfloat162_rn(make_float2(f0.z, f0.w));
    __nv_bfloat162 h2 = __float22bfloat162_rn(make_float2(f1.x, f1.y));
    __nv_bfloat162 h3 = __float22bfloat162_rn(make_float2(f1.z, f1.w));
    float2 g0 = __bfloat1622float2(h0), g1 = __bfloat1622float2(h1);
    float2 g2 = __bfloat1622float2(h2), g3 = __bfloat1622float2(h3);
    __nv_bfloat162 l0 = __float22bfloat162_rn(make_float2(f0.x - g0.x, f0.y - g0.y));
    __nv_bfloat162 l1 = __float22bfloat162_rn(make_float2(f0.z - g1.x, f0.w - g1.y));
    __nv_bfloat162 l2 = __float22bfloat162_rn(make_float2(f1.x - g2.x, f1.y - g2.y));
    __nv_bfloat162 l3 = __float22bfloat162_rn(make_float2(f1.z - g3.x, f1.w - g3.y));
    *hi = make_uint4(*(uint32_t*)&h0, *(uint32_t*)&h1, *(uint32_t*)&h2, *(uint32_t*)&h3);
    *lo = make_uint4(*(uint32_t*)&l0, *(uint32_t*)&l1, *(uint32_t*)&l2, *(uint32_t*)&l3);
}

// K1: HMMA (mma.sync bf16-split, K=192) QK^T -> exp(score/8+bias) -> attn, pb, partials.
// 8 warps: 4(m) x 2(n); warp tile 32q x 64k-cols; frag m16n8k16.
__global__ __launch_bounds__(256, 2) void k1_scores(
    const float* __restrict__ qg, const float* __restrict__ kg,
    const float* __restrict__ bw, const int* __restrict__ ctx,
    const int* __restrict__ mem, const unsigned int* __restrict__ mask,
    float* __restrict__ attn, float* __restrict__ pb)
{
    extern __shared__ __align__(1024) char smc[];
    // bf16 tiles 128 rows x 64 cols (=128B/row), XOR-swizzled: Qhi,Qlo,Khi,Klo
    char* tQh = smc;          char* tQl = smc + 16384;
    char* tKh = smc + 32768;  char* tKl = smc + 49152;
    __shared__ float bwsh[32];
    __shared__ int mems[128], ctxs[128];

    const int tid = threadIdx.x, wid = tid >> 5, lane = tid & 31;
    const int kt = blockIdx.x, qt = blockIdx.y, bh = blockIdx.z;
    const int b = bh >> 4, h = bh & 15;

    if (tid < 32) bwsh[tid] = bw[tid * HH + h];
    if (tid < 128) {
        mems[tid] = mem[b * SS + kt * 128 + tid];
        ctxs[tid] = ctx[b * SS + qt * 128 + tid];
    }

    const float* qbase = qg + ((size_t)bh * SS + (size_t)qt * 128) * DD;
    const float* kbase = kg + ((size_t)bh * SS + (size_t)kt * 128) * DD;
#pragma unroll
    for (int it = 0; it < 4; it++) {
        int task = it * 256 + tid;        // 1024 tasks: row x 8-float seg
        int row = task >> 3, seg = task & 7;
        uint32_t off = (uint32_t)(row * 128 + ((seg * 16) ^ ((row & 7) << 4)));
        const float4* s = (const float4*)(qbase + row * DD + seg * 8);
        uint4 hi, lo;
        split8(s[0], s[1], &hi, &lo);
        *(uint4*)(tQh + off) = hi; *(uint4*)(tQl + off) = lo;
        s = (const float4*)(kbase + row * DD + seg * 8);
        split8(s[0], s[1], &hi, &lo);
        *(uint4*)(tKh + off) = hi; *(uint4*)(tKl + off) = lo;
    }
    __syncthreads();

    const int warp_m = wid >> 1, warp_n = wid & 1;
    const int g = lane >> 3, lr = lane & 7;

    // ldmatrix lane-address row components (swizzle-aware)
    // A (Q tiles): matrices {m0-7/k0-7, m8-15/k0-7, m0-7/k8-15, m8-15/k8-15}
    uint32_t aRow[2], aSw[2];
    const int aColHalf = (g >> 1) * 16;   // bytes
#pragma unroll
    for (int mi = 0; mi < 2; mi++) {
        int r = warp_m * 32 + mi * 16 + (g & 1) * 8 + lr;
        aRow[mi] = (uint32_t)(r * 128);
        aSw[mi] = (uint32_t)((r & 7) << 4);
    }
    // B (K tiles): matrices {n0-7/k0-7, n0-7/k8-15, n8-15/k0-7, n8-15/k8-15}
    uint32_t bRow[4], bSw[4];
    const int bColHalf = (g & 1) * 16;
#pragma unroll
    for (int np = 0; np < 4; np++) {
        int r = warp_n * 64 + np * 16 + (g >> 1) * 8 + lr;
        bRow[np] = (uint32_t)(r * 128);
        bSw[np] = (uint32_t)((r & 7) << 4);
    }

    const uint32_t uQh = smem_u32(tQh), uQl = smem_u32(tQl);
    const uint32_t uKh = smem_u32(tKh), uKl = smem_u32(tKl);

    float acc[2][8][4];
#pragma unroll
    for (int mi = 0; mi < 2; mi++)
#pragma unroll
        for (int ni = 0; ni < 8; ni++)
#pragma unroll
            for (int e = 0; e < 4; e++) acc[mi][ni][e] = 0.f;

#pragma unroll
    for (int ks = 0; ks < 12; ks++) {
        const uint32_t ua = (ks < 8) ? uQh : uQl;               // 0-7: Qhi, 8-11: Qlo
        const uint32_t ub = ((ks >> 2) == 1) ? uKl : uKh;       // 4-7: Klo, else Khi
        const int kbyte = (ks & 3) * 32;

        uint32_t a[2][4];
#pragma unroll
        for (int mi = 0; mi < 2; mi++) {
            uint32_t ad = ua + aRow[mi] + (uint32_t)((kbyte + aColHalf) ^ aSw[mi]);
            LDSM4(a[mi][0], a[mi][1], a[mi][2], a[mi][3], ad);
        }
        uint32_t bf[8][2];
#pragma unroll
        for (int np = 0; np < 4; np++) {
            uint32_t bd = ub + bRow[np] + (uint32_t)((kbyte + bColHalf) ^ bSw[np]);
            uint32_t r0, r1, r2, r3;
            LDSM4(r0, r1, r2, r3, bd);
            bf[np * 2][0] = r0;     bf[np * 2][1] = r1;
            bf[np * 2 + 1][0] = r2; bf[np * 2 + 1][1] = r3;
        }
#pragma unroll
        for (int mi = 0; mi < 2; mi++)
#pragma unroll
            for (int ni = 0; ni < 8; ni++)
                MMA16816(acc[mi][ni], a[mi], bf[ni]);
    }

    // epilogue from fragments
    const int kj0 = kt * 128;
    const int colbase = warp_n * 64 + (lane & 3) * 2;
#pragma unroll
    for (int mi = 0; mi < 2; mi++) {
        const int r0 = warp_m * 32 + mi * 16 + (lane >> 2);
        const int r1 = r0 + 8;
        const int qi0 = qt * 128 + r0, qi1 = qt * 128 + r1;
        const int c0 = ctxs[r0], c1 = ctxs[r1];
        const size_t ro0 = ((size_t)bh * SS + qi0) * SS + kj0;
        const size_t ro1 = ((size_t)bh * SS + qi1) * SS + kj0;
        const unsigned int* mr0 = mask + ((size_t)b * SS + qi0) * SS + kj0;
        const unsigned int* mr1 = mask + ((size_t)b * SS + qi1) * SS + kj0;
        float ps0 = 0.f, ps1 = 0.f;
#pragma unroll
        for (int ni = 0; ni < 8; ni++) {
            const int col = colbase + ni * 8;
            const float bw0 = bwsh[rp_bucket(mems[col]     - c0)];
            const float bw1 = bwsh[rp_bucket(mems[col + 1] - c0)];
            const float bw2 = bwsh[rp_bucket(mems[col]     - c1)];
            const float bw3 = bwsh[rp_bucket(mems[col + 1] - c1)];
            const uint2 m0 = *(const uint2*)(mr0 + col);
            const uint2 m1 = *(const uint2*)(mr1 + col);
            float e00 = m0.x ? 0.f : __expf(acc[mi][ni][0] * 0.125f + bw0);
            float e01 = m0.y ? 0.f : __expf(acc[mi][ni][1] * 0.125f + bw1);
            float e10 = m1.x ? 0.f : __expf(acc[mi][ni][2] * 0.125f + bw2);
            float e11 = m1.y ? 0.f : __expf(acc[mi][ni][3] * 0.125f + bw3);
            ps0 += e00 + e01;  ps1 += e10 + e11;
            *(float2*)(attn + ro0 + col) = make_float2(e00, e01);
            *(float2*)(attn + ro1 + col) = make_float2(e10, e11);
            *(float2*)(pb + ro0 + col) = make_float2(bw0, bw1);
            *(float2*)(pb + ro1 + col) = make_float2(bw2, bw3);
        }
        ps0 += __shfl_xor_sync(~0u, ps0, 1);  ps0 += __shfl_xor_sync(~0u, ps0, 2);
        ps1 += __shfl_xor_sync(~0u, ps1, 1);  ps1 += __shfl_xor_sync(~0u, ps1, 2);
        if ((lane & 3) == 0) {
            g_rowpart[((size_t)bh * SS + qi0) * 32 + kt * 2 + warp_n] = ps0;
            g_rowpart[((size_t)bh * SS + qi1) * 32 + kt * 2 + warp_n] = ps1;
        }
    }
}

// K2': finalize softmax: attn *= 1/rowsum (in place). 4 rows per CTA.
__global__ __launch_bounds__(256) void k2_scale(float* __restrict__ attn)
{
    __shared__ float inv[4];
    const size_t r0 = (size_t)blockIdx.x * 4;
    const int tid = threadIdx.x;
    if (tid < 4) {
        const float* pp = g_rowpart + (r0 + tid) * 32;
        float s = 0.f;
#pragma unroll
        for (int t = 0; t < 32; t++) s += pp[t];
        inv[tid] = 1.0f / s;
    }
    __syncthreads();
    float4* p = (float4*)attn + r0 * 512;
#pragma unroll
    for (int j = 0; j < 8; j++) {
        int idx = j * 256 + tid;
        float iv = inv[idx >> 9];
        float4 e = p[idx];
        e.x *= iv; e.y *= iv; e.z *= iv; e.w *= iv;
        p[idx] = e;
    }
}

// K3: output = attn @ V.  256 threads, tile 256q x 64d, micro 8x8, 2 CTAs/SM.
__global__ __launch_bounds__(256, 2) void k3_av(
    const float* __restrict__ attn, const float* __restrict__ vg,
    float* __restrict__ outp)
{
    extern __shared__ float smx[];
    float* As = smx;               // [64 k][264 q] swizzled
    float* Vs = smx + 64 * 264;    // [64 k][68 d]

    const int tid = threadIdx.x;
    const int qt = blockIdx.x, bh = blockIdx.y;
    const int ty = tid >> 3, tx = tid & 7;
    const int qr = ty << 3, dc = tx << 3;

    float2 acc[8][4];
#pragma unroll
    for (int i = 0; i < 8; i++)
#pragma unroll
        for (int j = 0; j < 4; j++) acc[i][j] = make_float2(0.f, 0.f);

    for (int kt = 0; kt < 32; kt++) {
        const float4* asrc = (const float4*)(attn + ((size_t)bh * SS + (size_t)qt * 256) * SS + kt * 64);
        const float4* vsrc = (const float4*)(vg + ((size_t)bh * SS + (size_t)kt * 64) * DD);
#pragma unroll
        for (int rep = 0; rep < 16; rep++) {
            int i4 = rep * 256 + tid;
            int row = i4 >> 4;
            int c4 = (i4 & 15) << 2;
            float4 e = asrc[row * 512 + (c4 >> 2)];
            int r = row ^ (((c4 >> 2) & 7) << 2);
            As[(c4+0)*264 + r] = e.x;  As[(c4+1)*264 + r] = e.y;
            As[(c4+2)*264 + r] = e.z;  As[(c4+3)*264 + r] = e.w;
        }
#pragma unroll
        for (int rep = 0; rep < 4; rep++) {
            int i4 = rep * 256 + tid;
            int row = i4 >> 4, c4 = (i4 & 15) << 2;
            *(float4*)(Vs + row * 68 + c4) = vsrc[row * 16 + (c4 >> 2)];
        }
        __syncthreads();

#pragma unroll 8
        for (int k = 0; k < 64; k++) {
            const float* Ak = As + k * 264;
            const float* Vk = Vs + k * 68 + dc;
            int fk = ((k >> 2) & 7) << 2;
            int rq = qr ^ fk;
            float4 a0 = *(const float4*)(Ak + rq);
            float4 a1 = *(const float4*)(Ak + (rq ^ 4));
            float4 v0 = *(const float4*)(Vk);
            float4 v1 = *(const float4*)(Vk + 4);
            float2 vp0 = make_float2(v0.x, v0.y), vp1 = make_float2(v0.z, v0.w);
            float2 vp2 = make_float2(v1.x, v1.y), vp3 = make_float2(v1.z, v1.w);
            float av[8] = {a0.x,a0.y,a0.z,a0.w,a1.x,a1.y,a1.z,a1.w};
#pragma unroll
            for (int i = 0; i < 8; i++) {
                float2 ap = make_float2(av[i], av[i]);
                acc[i][0] = ffma2(ap, vp0, acc[i][0]);
                acc[i][1] = ffma2(ap, vp1, acc[i][1]);
                acc[i][2] = ffma2(ap, vp2, acc[i][2]);
                acc[i][3] = ffma2(ap, vp3, acc[i][3]);
            }
        }
        __syncthreads();
    }

#pragma unroll
    for (int i = 0; i < 8; i++) {
        size_t off = ((size_t)bh * SS + (size_t)qt * 256 + qr + i) * DD + dc;
        *(float4*)(outp + off)     = make_float4(acc[i][0].x, acc[i][0].y, acc[i][1].x, acc[i][1].y);
        *(float4*)(outp + off + 4) = make_float4(acc[i][2].x, acc[i][2].y, acc[i][3].x, acc[i][3].y);
    }
}

extern "C" void kernel_launch(void* const* d_in, const int* in_sizes, int n_in,
                              void* d_out, int out_size)
{
    const float* q  = (const float*)d_in[0];
    const float* k  = (const float*)d_in[1];
    const float* v  = (const float*)d_in[2];
    const float* bw = (const float*)d_in[3];
    const int* ctx  = (const int*)d_in[4];
    const int* mem  = (const int*)d_in[5];
    const unsigned int* mask = (const unsigned int*)d_in[6];

    float* outp = (float*)d_out;                    // [2,16,2048,64]
    float* attn = outp + (size_t)2*16*2048*64;      // [2,16,2048,2048]
    float* pb   = attn + (size_t)2*16*2048*2048;    // [2,16,2048,2048]

    const int smem1 = 4 * 16384;                    // 64KB bf16 tiles
    const int smem3 = (64*264 + 64*68) * 4;
    cudaFuncSetAttribute(k1_scores, cudaFuncAttributeMaxDynamicSharedMemorySize, smem1);
    cudaFuncSetAttribute(k3_av,     cudaFuncAttributeMaxDynamicSharedMemorySize, smem3);

    dim3 g1(16, 16, 32);
    k1_scores<<<g1, 256, smem1>>>(q, k, bw, ctx, mem, mask, attn, pb);
    k2_scale<<<32*2048/4, 256>>>(attn);
    dim3 g3(8, 32);
    k3_av<<<g3, 256, smem3>>>(attn, v, outp);
}

// round 17
// speedup vs baseline: 1.4935x; 1.4935x over previous
#include <cuda_runtime.h>
#include <cuda_bf16.h>
#include <cstdint>
#include <cstddef>

#define SS 2048
#define DD 64
#define HH 16

// per-(bh,row, kt*2+warp_n) partial sums of exp: 32*2048*32 floats = 8MB
__device__ float g_rowpart[(size_t)32 * 2048 * 32];

static __device__ __forceinline__ uint32_t smem_u32(const void* p) {
    uint32_t a;
    asm("{ .reg .u64 t; cvta.to.shared.u64 t, %1; cvt.u32.u64 %0, t; }" : "=r"(a) : "l"(p));
    return a;
}

#define LDSM4(r0, r1, r2, r3, a) \
    asm volatile("ldmatrix.sync.aligned.m8n8.x4.shared.b16 {%0,%1,%2,%3}, [%4];" \
        : "=r"(r0), "=r"(r1), "=r"(r2), "=r"(r3) : "r"(a))

#define MMA16816(c, a, b) \
    asm volatile("mma.sync.aligned.m16n8k16.row.col.f32.bf16.bf16.f32 " \
        "{%0,%1,%2,%3}, {%4,%5,%6,%7}, {%8,%9}, {%0,%1,%2,%3};" \
        : "+f"((c)[0]), "+f"((c)[1]), "+f"((c)[2]), "+f"((c)[3]) \
        : "r"((a)[0]), "r"((a)[1]), "r"((a)[2]), "r"((a)[3]), "r"((b)[0]), "r"((b)[1]))

static __device__ __forceinline__ float2 ffma2(float2 a, float2 b, float2 c) {
    unsigned long long ua = *reinterpret_cast<unsigned long long*>(&a);
    unsigned long long ub = *reinterpret_cast<unsigned long long*>(&b);
    unsigned long long uc = *reinterpret_cast<unsigned long long*>(&c);
    unsigned long long ud;
    asm("fma.rn.f32x2 %0, %1, %2, %3;" : "=l"(ud) : "l"(ua), "l"(ub), "l"(uc));
    return *reinterpret_cast<float2*>(&ud);
}

// T5 bidirectional bucket, NUM_BUCKETS=32, MAX_DISTANCE=128 (exact int thresholds)
static __device__ __forceinline__ int rp_bucket(int rel) {
    int n = -rel;
    int ret = (n < 0) ? 16 : 0;
    n = abs(n);
    if (n < 8) return ret + n;
    return ret + 8 + (n >= 12) + (n >= 16) + (n >= 23) + (n >= 32)
                   + (n >= 46) + (n >= 64) + (n >= 91);
}

// split 8 f32 -> 8 bf16 hi + 8 bf16 lo
static __device__ __forceinline__ void split8(
    const float4 f0, const float4 f1, uint4* hi, uint4* lo)
{
    __nv_bfloat162 h0 = __float22bfloat162_rn(make_float2(f0.x, f0.y));
    __nv_bfloat162 h1 = __float22bfloat162_rn(make_float2(f0.z, f0.w));
    __nv_bfloat162 h2 = __float22bfloat162_rn(make_float2(f1.x, f1.y));
    __nv_bfloat162 h3 = __float22bfloat162_rn(make_float2(f1.z, f1.w));
    float2 g0 = __bfloat1622float2(h0), g1 = __bfloat1622float2(h1);
    float2 g2 = __bfloat1622float2(h2), g3 = __bfloat1622float2(h3);
    __nv_bfloat162 l0 = __float22bfloat162_rn(make_float2(f0.x - g0.x, f0.y - g0.y));
    __nv_bfloat162 l1 = __float22bfloat162_rn(make_float2(f0.z - g1.x, f0.w - g1.y));
    __nv_bfloat162 l2 = __float22bfloat162_rn(make_float2(f1.x - g2.x, f1.y - g2.y));
    __nv_bfloat162 l3 = __float22bfloat162_rn(make_float2(f1.z - g3.x, f1.w - g3.y));
    *hi = make_uint4(*(uint32_t*)&h0, *(uint32_t*)&h1, *(uint32_t*)&h2, *(uint32_t*)&h3);
    *lo = make_uint4(*(uint32_t*)&l0, *(uint32_t*)&l1, *(uint32_t*)&l2, *(uint32_t*)&l3);
}

// K1: HMMA bf16-split QK^T -> exp(score/8+bias) -> attn + rowpart.
// Bias via per-tile diagonal table (positions are arange).
__global__ __launch_bounds__(256, 2) void k1_scores(
    const float* __restrict__ qg, const float* __restrict__ kg,
    const float* __restrict__ bw, const unsigned int* __restrict__ mask,
    float* __restrict__ attn)
{
    extern __shared__ __align__(1024) char smc[];
    char* tQh = smc;          char* tQl = smc + 16384;
    char* tKh = smc + 32768;  char* tKl = smc + 49152;
    __shared__ float bwsh[32];
    __shared__ float btab[255];   // bias for rel = kdiff + (t-127)

    const int tid = threadIdx.x, wid = tid >> 5, lane = tid & 31;
    const int kt = blockIdx.x, qt = blockIdx.y, bh = blockIdx.z;
    const int b = bh >> 4, h = bh & 15;
    const int kdiff = kt * 128 - qt * 128;

    if (tid < 32) bwsh[tid] = bw[tid * HH + h];

    const float* qbase = qg + ((size_t)bh * SS + (size_t)qt * 128) * DD;
    const float* kbase = kg + ((size_t)bh * SS + (size_t)kt * 128) * DD;
#pragma unroll
    for (int it = 0; it < 4; it++) {
        int task = it * 256 + tid;
        int row = task >> 3, seg = task & 7;
        uint32_t off = (uint32_t)(row * 128 + ((seg * 16) ^ ((row & 7) << 4)));
        const float4* s = (const float4*)(qbase + row * DD + seg * 8);
        uint4 hi, lo;
        split8(s[0], s[1], &hi, &lo);
        *(uint4*)(tQh + off) = hi; *(uint4*)(tQl + off) = lo;
        s = (const float4*)(kbase + row * DD + seg * 8);
        split8(s[0], s[1], &hi, &lo);
        *(uint4*)(tKh + off) = hi; *(uint4*)(tKl + off) = lo;
    }
    __syncthreads();
    if (tid < 255) btab[tid] = bwsh[rp_bucket(kdiff + tid - 127)];
    __syncthreads();

    const int warp_m = wid >> 1, warp_n = wid & 1;
    const int g = lane >> 3, lr = lane & 7;

    uint32_t aRow[2], aSw[2];
    const int aColHalf = (g >> 1) * 16;
#pragma unroll
    for (int mi = 0; mi < 2; mi++) {
        int r = warp_m * 32 + mi * 16 + (g & 1) * 8 + lr;
        aRow[mi] = (uint32_t)(r * 128);
        aSw[mi] = (uint32_t)((r & 7) << 4);
    }
    uint32_t bRow[4], bSw[4];
    const int bColHalf = (g & 1) * 16;
#pragma unroll
    for (int np = 0; np < 4; np++) {
        int r = warp_n * 64 + np * 16 + (g >> 1) * 8 + lr;
        bRow[np] = (uint32_t)(r * 128);
        bSw[np] = (uint32_t)((r & 7) << 4);
    }

    const uint32_t uQh = smem_u32(tQh), uQl = smem_u32(tQl);
    const uint32_t uKh = smem_u32(tKh), uKl = smem_u32(tKl);

    float acc[2][8][4];
#pragma unroll
    for (int mi = 0; mi < 2; mi++)
#pragma unroll
        for (int ni = 0; ni < 8; ni++)
#pragma unroll
            for (int e = 0; e < 4; e++) acc[mi][ni][e] = 0.f;

#pragma unroll
    for (int ks = 0; ks < 12; ks++) {
        const uint32_t ua = (ks < 8) ? uQh : uQl;
        const uint32_t ub = ((ks >> 2) == 1) ? uKl : uKh;
        const int kbyte = (ks & 3) * 32;
        uint32_t a[2][4];
#pragma unroll
        for (int mi = 0; mi < 2; mi++) {
            uint32_t ad = ua + aRow[mi] + (uint32_t)((kbyte + aColHalf) ^ aSw[mi]);
            LDSM4(a[mi][0], a[mi][1], a[mi][2], a[mi][3], ad);
        }
        uint32_t bf[8][2];
#pragma unroll
        for (int np = 0; np < 4; np++) {
            uint32_t bd = ub + bRow[np] + (uint32_t)((kbyte + bColHalf) ^ bSw[np]);
            uint32_t r0, r1, r2, r3;
            LDSM4(r0, r1, r2, r3, bd);
            bf[np * 2][0] = r0;     bf[np * 2][1] = r1;
            bf[np * 2 + 1][0] = r2; bf[np * 2 + 1][1] = r3;
        }
#pragma unroll
        for (int mi = 0; mi < 2; mi++)
#pragma unroll
            for (int ni = 0; ni < 8; ni++)
                MMA16816(acc[mi][ni], a[mi], bf[ni]);
    }

    // epilogue: bias from btab[col - row + 127]
    const int kj0 = kt * 128;
    const int colbase = warp_n * 64 + (lane & 3) * 2;
#pragma unroll
    for (int mi = 0; mi < 2; mi++) {
        const int r0 = warp_m * 32 + mi * 16 + (lane >> 2);
        const int r1 = r0 + 8;
        const int qi0 = qt * 128 + r0, qi1 = qt * 128 + r1;
        const size_t ro0 = ((size_t)bh * SS + qi0) * SS + kj0;
        const size_t ro1 = ((size_t)bh * SS + qi1) * SS + kj0;
        const unsigned int* mr0 = mask + ((size_t)b * SS + qi0) * SS + kj0;
        const unsigned int* mr1 = mask + ((size_t)b * SS + qi1) * SS + kj0;
        float ps0 = 0.f, ps1 = 0.f;
#pragma unroll
        for (int ni = 0; ni < 8; ni++) {
            const int col = colbase + ni * 8;
            const int t0 = col - r0 + 127;
            const float bw0 = btab[t0],     bw1 = btab[t0 + 1];
            const float bw2 = btab[t0 - 8], bw3 = btab[t0 - 7];
            const uint2 m0 = *(const uint2*)(mr0 + col);
            const uint2 m1 = *(const uint2*)(mr1 + col);
            float e00 = m0.x ? 0.f : __expf(acc[mi][ni][0] * 0.125f + bw0);
            float e01 = m0.y ? 0.f : __expf(acc[mi][ni][1] * 0.125f + bw1);
            float e10 = m1.x ? 0.f : __expf(acc[mi][ni][2] * 0.125f + bw2);
            float e11 = m1.y ? 0.f : __expf(acc[mi][ni][3] * 0.125f + bw3);
            ps0 += e00 + e01;  ps1 += e10 + e11;
            *(float2*)(attn + ro0 + col) = make_float2(e00, e01);
            *(float2*)(attn + ro1 + col) = make_float2(e10, e11);
        }
        ps0 += __shfl_xor_sync(~0u, ps0, 1);  ps0 += __shfl_xor_sync(~0u, ps0, 2);
        ps1 += __shfl_xor_sync(~0u, ps1, 1);  ps1 += __shfl_xor_sync(~0u, ps1, 2);
        if ((lane & 3) == 0) {
            g_rowpart[((size_t)bh * SS + qi0) * 32 + kt * 2 + warp_n] = ps0;
            g_rowpart[((size_t)bh * SS + qi1) * 32 + kt * 2 + warp_n] = ps1;
        }
    }
}

// K3: normalize attn (writeback) + write pb from diagonal table + output = attn@V.
// 256 threads, tile 256q x 64d, micro 8x8, 2 CTAs/SM.
__global__ __launch_bounds__(256, 2) void k3_av(
    float* __restrict__ attn, const float* __restrict__ vg,
    const float* __restrict__ bw, float* __restrict__ outp,
    float* __restrict__ pb)
{
    extern __shared__ float smx[];
    float* As = smx;               // [64 k][264 q] swizzled
    float* Vs = smx + 64 * 264;    // [64 k][68 d]
    __shared__ float bwsh[32];
    __shared__ float rowInv[256];
    __shared__ float ptab[2303];   // bias for (row,col): ptab[col - row + 255]

    const int tid = threadIdx.x;
    const int qt = blockIdx.x, bh = blockIdx.y;
    const int h = bh & 15;
    const int q0 = qt * 256;
    const int ty = tid >> 3, tx = tid & 7;
    const int qr = ty << 3, dc = tx << 3;

    if (tid < 32) bwsh[tid] = bw[tid * HH + h];
    {
        const float* pp = g_rowpart + ((size_t)bh * SS + q0 + tid) * 32;
        float s = 0.f;
#pragma unroll
        for (int t = 0; t < 32; t++) s += pp[t];
        rowInv[tid] = 1.0f / s;
    }
    __syncthreads();
    for (int t = tid; t < 2303; t += 256)
        ptab[t] = bwsh[rp_bucket(t - 255 - q0)];
    __syncthreads();

    float2 acc[8][4];
#pragma unroll
    for (int i = 0; i < 8; i++)
#pragma unroll
        for (int j = 0; j < 4; j++) acc[i][j] = make_float2(0.f, 0.f);

    for (int kt = 0; kt < 32; kt++) {
        float4* asrc = (float4*)(attn + ((size_t)bh * SS + (size_t)q0) * SS + kt * 64);
        float* pbase = pb + ((size_t)bh * SS + (size_t)q0) * SS + kt * 64;
        const float4* vsrc = (const float4*)(vg + ((size_t)bh * SS + (size_t)kt * 64) * DD);
#pragma unroll
        for (int rep = 0; rep < 16; rep++) {
            int i4 = rep * 256 + tid;
            int row = i4 >> 4;
            int c4 = (i4 & 15) << 2;
            float4 e = asrc[row * 512 + (c4 >> 2)];
            float inv = rowInv[row];
            e.x *= inv; e.y *= inv; e.z *= inv; e.w *= inv;
            asrc[row * 512 + (c4 >> 2)] = e;              // softmax writeback
            int r = row ^ (((c4 >> 2) & 7) << 2);
            As[(c4+0)*264 + r] = e.x;  As[(c4+1)*264 + r] = e.y;
            As[(c4+2)*264 + r] = e.z;  As[(c4+3)*264 + r] = e.w;
            // position_bias write for (row, kt*64 + c4 .. +3)
            int t0 = kt * 64 + c4 - row + 255;
            *(float4*)(pbase + (size_t)row * SS + c4) =
                make_float4(ptab[t0], ptab[t0+1], ptab[t0+2], ptab[t0+3]);
        }
#pragma unroll
        for (int rep = 0; rep < 4; rep++) {
            int i4 = rep * 256 + tid;
            int row = i4 >> 4, c4 = (i4 & 15) << 2;
            *(float4*)(Vs + row * 68 + c4) = vsrc[row * 16 + (c4 >> 2)];
        }
        __syncthreads();

#pragma unroll 8
        for (int k = 0; k < 64; k++) {
            const float* Ak = As + k * 264;
            const float* Vk = Vs + k * 68 + dc;
            int fk = ((k >> 2) & 7) << 2;
            int rq = qr ^ fk;
            float4 a0 = *(const float4*)(Ak + rq);
            float4 a1 = *(const float4*)(Ak + (rq ^ 4));
            float4 v0 = *(const float4*)(Vk);
            float4 v1 = *(const float4*)(Vk + 4);
            float2 vp0 = make_float2(v0.x, v0.y), vp1 = make_float2(v0.z, v0.w);
            float2 vp2 = make_float2(v1.x, v1.y), vp3 = make_float2(v1.z, v1.w);
            float av[8] = {a0.x,a0.y,a0.z,a0.w,a1.x,a1.y,a1.z,a1.w};
#pragma unroll
            for (int i = 0; i < 8; i++) {
                float2 ap = make_float2(av[i], av[i]);
                acc[i][0] = ffma2(ap, vp0, acc[i][0]);
                acc[i][1] = ffma2(ap, vp1, acc[i][1]);
                acc[i][2] = ffma2(ap, vp2, acc[i][2]);
                acc[i][3] = ffma2(ap, vp3, acc[i][3]);
            }
        }
        __syncthreads();
    }

#pragma unroll
    for (int i = 0; i < 8; i++) {
        size_t off = ((size_t)bh * SS + (size_t)q0 + qr + i) * DD + dc;
        *(float4*)(outp + off)     = make_float4(acc[i][0].x, acc[i][0].y, acc[i][1].x, acc[i][1].y);
        *(float4*)(outp + off + 4) = make_float4(acc[i][2].x, acc[i][2].y, acc[i][3].x, acc[i][3].y);
    }
}

extern "C" void kernel_launch(void* const* d_in, const int* in_sizes, int n_in,
                              void* d_out, int out_size)
{
    const float* q  = (const float*)d_in[0];
    const float* k  = (const float*)d_in[1];
    const float* v  = (const float*)d_in[2];
    const float* bw = (const float*)d_in[3];
    const unsigned int* mask = (const unsigned int*)d_in[6];

    float* outp = (float*)d_out;                    // [2,16,2048,64]
    float* attn = outp + (size_t)2*16*2048*64;      // [2,16,2048,2048]
    float* pb   = attn + (size_t)2*16*2048*2048;    // [2,16,2048,2048]

    const int smem1 = 4 * 16384;                    // 64KB bf16 tiles
    const int smem3 = (64*264 + 64*68) * 4;
    cudaFuncSetAttribute(k1_scores, cudaFuncAttributeMaxDynamicSharedMemorySize, smem1);
    cudaFuncSetAttribute(k3_av,     cudaFuncAttributeMaxDynamicSharedMemorySize, smem3);

    dim3 g1(16, 16, 32);
    k1_scores<<<g1, 256, smem1>>>(q, k, bw, mask, attn);
    dim3 g3(8, 32);
    k3_av<<<g3, 256, smem3>>>(attn, v, bw, outp, pb);
}